// round 9
// baseline (speedup 1.0000x reference)
#include <cuda_runtime.h>
#include <math.h>
#include <stdint.h>

// Problem constants
#define NTH   512
#define PAD   65
#define NV    16
#define ND    64
#define NH    256
#define NC    128
#define NTOK  8192
#define TT    64     // wg token tile
#define GT    128    // xt token tile
#define GTOK  64     // gemm token tile
#define BK    16     // gemm k-chunk (2 mma k-steps)
#define NS    3      // pipeline stages
#define SP    132    // xt smem pad
#define TX    68     // xs row stride (pad)

typedef unsigned long long u64;

// Scratch (device globals: allocation-free rule)
__device__ float g_ctxp[32 * NH];
__device__ float g_xT[NV * ND * NTOK];        // x transposed [v][d][n]
__device__ float g_h1[NV * NH * NTOK];        // elu(fc1) [v][c][n]
__device__ float g_res[NV * NH * NTOK];       // skip residual [v][c][n]
__device__ float g_h2[NV * NH * NTOK];        // fc2 out [v][c][n]
__device__ float g_a[NV * NH * NTOK];         // glu a-half [v][c][n]
__device__ float g_hv[NTOK * NV * NH];        // raw hv (pre-LN) [n][v][c]

// Pre-split, fragment-linear tf32 weights: [v][kstep][tile][lane]{hi0,hi1,lo0,lo1}
__device__ float g_wf_fc1[16 * 8  * 4096];    // fc1:  K=64,  N=256
__device__ float g_wf_sk [16 * 8  * 4096];    // skip: K=64,  N=256
__device__ float g_wf_fc2[16 * 32 * 4096];    // fc2:  K=256, N=256
__device__ float g_wf_glu[16 * 32 * 8192];    // glu:  K=256, N=512

__device__ __forceinline__ float elu_f(float x)  { return x > 0.f ? x : (__expf(x) - 1.f); }
__device__ __forceinline__ float sigm_f(float x) { return 1.f / (1.f + __expf(-x)); }
__device__ __forceinline__ float idf(float x)    { return x; }

// ---- 3xTF32 split ----
__device__ __forceinline__ void split_tf32(float x, unsigned& hi, unsigned& lo) {
    asm("cvt.rna.tf32.f32 %0, %1;" : "=r"(hi) : "f"(x));
    float l = x - __uint_as_float(hi);
    asm("cvt.rna.tf32.f32 %0, %1;" : "=r"(lo) : "f"(l));
}

#define MMA_T(D, A0, A1, A2, A3, B0, B1) \
    asm volatile("mma.sync.aligned.m16n8k8.row.col.f32.tf32.tf32.f32 " \
        "{%0,%1,%2,%3}, {%4,%5,%6,%7}, {%8,%9}, {%0,%1,%2,%3};" \
        : "+f"((D)[0]), "+f"((D)[1]), "+f"((D)[2]), "+f"((D)[3]) \
        : "r"(A0), "r"(A1), "r"(A2), "r"(A3), "r"(B0), "r"(B1))

// ---- packed fp32x2 helpers (wg kernel) ----
__device__ __forceinline__ u64 pk2(float a, float b) {
    u64 r; asm("mov.b64 %0, {%1, %2};" : "=l"(r) : "f"(a), "f"(b)); return r;
}
__device__ __forceinline__ void fm2(u64& d, u64 a, u64 b) {
    asm("fma.rn.f32x2 %0, %1, %2, %0;" : "+l"(d) : "l"(a), "l"(b));
}
__device__ __forceinline__ float2 up2(u64 v) {
    float2 f; asm("mov.b64 {%0, %1}, %2;" : "=f"(f.x), "=f"(f.y) : "l"(v)); return f;
}

// ---- cp.async helpers ----
__device__ __forceinline__ void cpa16(unsigned int s, const void* g) {
    asm volatile("cp.async.cg.shared.global [%0], [%1], 16;" :: "r"(s), "l"(g));
}
#define CPA_COMMIT() asm volatile("cp.async.commit_group;" ::: "memory")
#define CPA_WAIT(n)  asm volatile("cp.async.wait_group %0;" :: "n"(n) : "memory")

// ===========================================================================
// Tensor GEMM core: block = 64 tokens x 256 cols, 256 threads (8 warps),
// 2 blocks/SM. Warp = 16 tokens x 128 cols = 16 m16n8 tiles (3xTF32).
// smem: NS stages of xs[BK][TX] (raw x) + ws[2][4096] frag weights.
// ===========================================================================
#define G_SMEM_T ((NS * BK * TX + NS * 8192) * 4)   // 111360 B

#define GDECL_T \
    extern __shared__ float smem[]; \
    float* xs = smem; \
    float* ws = smem + NS * BK * TX; \
    const unsigned int xs_u = (unsigned int)__cvta_generic_to_shared(xs); \
    const unsigned int ws_u = (unsigned int)__cvta_generic_to_shared(ws); \
    const int tid  = threadIdx.x; \
    const int lane = tid & 31, warp = tid >> 5; \
    const int kq   = lane & 3,  lq   = lane >> 2; \
    const int tok0 = (warp & 3) * 16; \
    const int ch   = warp >> 2; \
    const int v    = blockIdx.y; \
    const int n0   = blockIdx.x * GTOK; \
    float d[16][4];

#define GZERO_T() do { \
    _Pragma("unroll") for (int _t = 0; _t < 16; ++_t) \
    _Pragma("unroll") for (int _i = 0; _i < 4; ++_i) d[_t][_i] = 0.f; \
} while (0)

// x: 16 rows x 64 floats; w frags: 2 ksteps x 4096 floats (contiguous gmem)
#define ISSUE_T(APTR, WFP, WSTEP_, kc, buf) do { \
    { int kr = tid >> 4, cc2 = tid & 15; \
      cpa16(xs_u + (((buf) * BK + kr) * TX + cc2 * 4) * 4, \
            (APTR) + (size_t)((kc) * BK + kr) * NTOK + cc2 * 4); } \
    _Pragma("unroll") \
    for (int jj = 0; jj < 2; ++jj) { \
      _Pragma("unroll") \
      for (int ii = 0; ii < 4; ++ii) { \
        int off = ii * 1024 + tid * 4; \
        cpa16(ws_u + (((buf) * 2 + jj) * 4096 + off) * 4, \
              (WFP) + (size_t)(2 * (kc) + jj) * (WSTEP_) + off); } } \
} while (0)

#define GCHUNK_T(buf) do { \
    const float* xb = xs + (buf) * BK * TX; \
    _Pragma("unroll") \
    for (int ks = 0; ks < 2; ++ks) { \
        unsigned ah0, ah1, ah2, ah3, al0, al1, al2, al3; \
        { float r0 = xb[(ks * 8 + kq) * TX + tok0 + lq]; \
          float r1 = xb[(ks * 8 + kq) * TX + tok0 + lq + 8]; \
          float r2 = xb[(ks * 8 + kq + 4) * TX + tok0 + lq]; \
          float r3 = xb[(ks * 8 + kq + 4) * TX + tok0 + lq + 8]; \
          split_tf32(r0, ah0, al0); split_tf32(r1, ah1, al1); \
          split_tf32(r2, ah2, al2); split_tf32(r3, ah3, al3); } \
        const float4* wk = reinterpret_cast<const float4*>( \
            ws + ((buf) * 2 + ks) * 4096 + ch * 2048) + lane; \
        _Pragma("unroll") \
        for (int t = 0; t < 16; ++t) { \
            float4 bf = wk[t * 32]; \
            unsigned bh0 = __float_as_uint(bf.x), bh1 = __float_as_uint(bf.y); \
            unsigned bl0 = __float_as_uint(bf.z), bl1 = __float_as_uint(bf.w); \
            MMA_T(d[t], ah0, ah1, ah2, ah3, bh0, bh1); \
            MMA_T(d[t], ah0, ah1, ah2, ah3, bl0, bl1); \
            MMA_T(d[t], al0, al1, al2, al3, bh0, bh1); \
        } \
    } \
} while (0)

#define GRUN_T(APTR, WFP, WSTEP_, KN) do { \
    const int nkc = (KN) / BK; \
    _Pragma("unroll") \
    for (int p = 0; p < NS - 1; ++p) { \
        if (p < nkc) { ISSUE_T(APTR, WFP, WSTEP_, p, p); CPA_COMMIT(); } \
    } \
    for (int kc = 0; kc < nkc; ++kc) { \
        CPA_WAIT(NS - 2); \
        __syncthreads(); \
        if (kc + NS - 1 < nkc) { \
            ISSUE_T(APTR, WFP, WSTEP_, kc + NS - 1, (kc + NS - 1) % NS); \
            CPA_COMMIT(); \
        } \
        GCHUNK_T(kc % NS); \
    } \
} while (0)

// Transpose accumulators into smem [col][68] (conflict-free STS)
#define TEPI_SM() do { \
    __syncthreads(); \
    _Pragma("unroll") \
    for (int t = 0; t < 16; ++t) { \
        int cc = ch * 128 + t * 8 + 2 * kq; \
        int tr = tok0 + lq; \
        smem[cc * 68 + tr]           = d[t][0]; \
        smem[(cc + 1) * 68 + tr]     = d[t][1]; \
        smem[cc * 68 + tr + 8]       = d[t][2]; \
        smem[(cc + 1) * 68 + tr + 8] = d[t][3]; \
    } \
    __syncthreads(); \
} while (0)

// Epilogue: bias + OP, coalesced store to [c][NTOK]
#define GEPI_T(OUTP, BIASP, OP) do { \
    TEPI_SM(); \
    for (int cb = 0; cb < 32; ++cb) { \
        int col = warp + cb * 8; \
        float bb = (BIASP)[col]; \
        float* dp = (OUTP) + (size_t)col * NTOK + n0; \
        dp[lane]      = OP(smem[col * 68 + lane] + bb); \
        dp[32 + lane] = OP(smem[col * 68 + 32 + lane] + bb); \
    } \
    __syncthreads(); \
} while (0)

// ---------------------------------------------------------------------------
// Weight prep: split to tf32 hi/lo, fragment-linear layout.
// sel: 0=fc1, 1=skip, 2=fc2, 3=glu
// ---------------------------------------------------------------------------
__global__ void wprep(const float* __restrict__ W, int K, int N, int sel)
{
    float* F = (sel == 0) ? g_wf_fc1 : (sel == 1) ? g_wf_sk :
               (sel == 2) ? g_wf_fc2 : g_wf_glu;
    const int T = N / 8;
    const int total = (K / 8) * T * 32;
    int idx = blockIdx.x * 256 + threadIdx.x;
    if (idx >= total) return;
    int lane = idx & 31;
    int rest = idx >> 5;
    int t = rest % T, s = rest / T;
    int kq = lane & 3, lq = lane >> 2;
    const float* Wv = W + (size_t)blockIdx.y * K * N;
    float w0 = Wv[(size_t)(s * 8 + kq) * N + t * 8 + lq];
    float w1 = Wv[(size_t)(s * 8 + kq + 4) * N + t * 8 + lq];
    unsigned h0, l0, h1, l1;
    split_tf32(w0, h0, l0);
    split_tf32(w1, h1, l1);
    float4 o = make_float4(__uint_as_float(h0), __uint_as_float(h1),
                           __uint_as_float(l0), __uint_as_float(l1));
    *(float4*)(F + ((size_t)blockIdx.y * total + idx) * 4) = o;
}

// ---------------------------------------------------------------------------
// Kernel 0: context projection
// ---------------------------------------------------------------------------
__global__ void ctx_kernel(const float* __restrict__ ctx, const float* __restrict__ wctx)
{
    int b = blockIdx.x;
    int h = threadIdx.x;
    float acc = 0.f;
    for (int c = 0; c < NC; ++c)
        acc += ctx[b * NC + c] * wctx[c * NH + h];
    g_ctxp[b * NH + h] = acc;
}

// ---------------------------------------------------------------------------
// Kernel: transpose x[n][v][d] -> g_xT[v][d][n]
// ---------------------------------------------------------------------------
__global__ void xt_kernel(const float* __restrict__ x)
{
    __shared__ float s[64 * SP];
    const int v  = blockIdx.y;
    const int n0 = blockIdx.x * GT;
    const int tid = threadIdx.x;

#pragma unroll
    for (int r = 0; r < 8; ++r) {
        int idx = tid + r * 256;
        int t  = idx >> 4;
        int dq = idx & 15;
        float4 val = *(const float4*)(x + (size_t)(n0 + t) * 1024 + v * 64 + dq * 4);
        s[(dq * 4 + 0) * SP + t] = val.x;
        s[(dq * 4 + 1) * SP + t] = val.y;
        s[(dq * 4 + 2) * SP + t] = val.z;
        s[(dq * 4 + 3) * SP + t] = val.w;
    }
    __syncthreads();
#pragma unroll
    for (int r = 0; r < 8; ++r) {
        int idx = tid + r * 256;
        int d  = idx >> 5;
        int tq = idx & 31;
        float4 o = *(const float4*)(s + d * SP + tq * 4);
        *(float4*)(g_xT + ((size_t)v * ND + d) * NTOK + n0 + tq * 4) = o;
    }
}

// ---------------------------------------------------------------------------
// Kernel 1: weight GRN -> softmax weights (FFMA2 path, unchanged)
// ---------------------------------------------------------------------------
#define GSTEP(ACC) do { \
    u64 _xp; \
    _xp = pk2(xs0, xs0); fm2(ACC[0][0], wA.x, _xp); fm2(ACC[0][1], wA.y, _xp); fm2(ACC[0][2], wB.x, _xp); fm2(ACC[0][3], wB.y, _xp); \
    _xp = pk2(xs1, xs1); fm2(ACC[1][0], wA.x, _xp); fm2(ACC[1][1], wA.y, _xp); fm2(ACC[1][2], wB.x, _xp); fm2(ACC[1][3], wB.y, _xp); \
    _xp = pk2(xs2, xs2); fm2(ACC[2][0], wA.x, _xp); fm2(ACC[2][1], wA.y, _xp); fm2(ACC[2][2], wB.x, _xp); fm2(ACC[2][3], wB.y, _xp); \
    _xp = pk2(xs3, xs3); fm2(ACC[3][0], wA.x, _xp); fm2(ACC[3][1], wA.y, _xp); fm2(ACC[3][2], wB.x, _xp); fm2(ACC[3][3], wB.y, _xp); \
} while (0)

#define ZERO44(ACC) do { \
    _Pragma("unroll") for (int _i = 0; _i < 4; ++_i) \
    _Pragma("unroll") for (int _j = 0; _j < 4; ++_j) ACC[_i][_j] = 0ull; \
} while (0)

__global__ __launch_bounds__(NTH, 1)
void wg_kernel(const float* __restrict__ x,
               const float* __restrict__ fc1w, const float* __restrict__ fc1b,
               const float* __restrict__ fc2w, const float* __restrict__ fc2b,
               const float* __restrict__ gluw, const float* __restrict__ glub,
               const float* __restrict__ skw,  const float* __restrict__ skb,
               const float* __restrict__ lng,  const float* __restrict__ lnb,
               float* __restrict__ outw)
{
    extern __shared__ float sm[];
    float* sx  = sm;                       // [128][PAD]
    float* ash = sx  + 128 * PAD;          // [256][PAD]
    float* bsh = ash + 256 * PAD;          // [256][PAD]
    float* rsh = bsh + 256 * PAD;          // [64][16]
    float* gsh = rsh + 64 * 16;            // [64][32]

    const int tid  = threadIdx.x;
    const int warp = tid >> 5, lane = tid & 31;
    const int t0 = warp * 4;
    const int c0 = lane * 8;
    const int n0 = blockIdx.x * TT;
    const int tR = tid >> 3, jR = tid & 7;

    u64 acc[4][4];
    ZERO44(acc);
    float r0 = 0.f, r1 = 0.f;

    for (int kt = 0; kt < 8; ++kt) {
        for (int i = tid; i < TT * 128; i += NTH) {
            int t = i >> 7, k = i & 127;
            sx[k * PAD + t] = x[(size_t)(n0 + t) * 1024 + kt * 128 + k];
        }
        __syncthreads();
        const float* W = fc1w + (size_t)(kt * 128) * NH + c0;
#pragma unroll 2
        for (int k = 0; k < 128; ++k) {
            ulonglong2 wA = *(const ulonglong2*)(W + (size_t)k * NH);
            ulonglong2 wB = *(const ulonglong2*)(W + (size_t)k * NH + 4);
            float xs0 = sx[k * PAD + t0 + 0];
            float xs1 = sx[k * PAD + t0 + 1];
            float xs2 = sx[k * PAD + t0 + 2];
            float xs3 = sx[k * PAD + t0 + 3];
            GSTEP(acc);
        }
        const float* Ws = skw + (size_t)(kt * 128) * NV;
#pragma unroll 4
        for (int k = 0; k < 128; ++k) {
            float xv = sx[k * PAD + tR];
            r0 += xv * Ws[k * NV + jR];
            r1 += xv * Ws[k * NV + jR + 8];
        }
        __syncthreads();
    }

    {
        const int b = n0 >> 8;
#pragma unroll
        for (int j = 0; j < 4; ++j) {
            int ca = c0 + 2 * j, cb = ca + 1;
            float ba = fc1b[ca] + g_ctxp[b * NH + ca];
            float bb = fc1b[cb] + g_ctxp[b * NH + cb];
#pragma unroll
            for (int i = 0; i < 4; ++i) {
                float2 p = up2(acc[i][j]);
                ash[ca * PAD + t0 + i] = elu_f(p.x + ba);
                ash[cb * PAD + t0 + i] = elu_f(p.y + bb);
            }
        }
        rsh[tR * 16 + jR]     = r0 + skb[jR];
        rsh[tR * 16 + jR + 8] = r1 + skb[jR + 8];
    }
    __syncthreads();

    ZERO44(acc);
    {
        const float* W2 = fc2w + c0;
#pragma unroll 2
        for (int k = 0; k < NH; ++k) {
            ulonglong2 wA = *(const ulonglong2*)(W2 + (size_t)k * NH);
            ulonglong2 wB = *(const ulonglong2*)(W2 + (size_t)k * NH + 4);
            float xs0 = ash[k * PAD + t0 + 0];
            float xs1 = ash[k * PAD + t0 + 1];
            float xs2 = ash[k * PAD + t0 + 2];
            float xs3 = ash[k * PAD + t0 + 3];
            GSTEP(acc);
        }
#pragma unroll
        for (int j = 0; j < 4; ++j) {
            int ca = c0 + 2 * j, cb = ca + 1;
            float ba = fc2b[ca], bb = fc2b[cb];
#pragma unroll
            for (int i = 0; i < 4; ++i) {
                float2 p = up2(acc[i][j]);
                bsh[ca * PAD + t0 + i] = p.x + ba;
                bsh[cb * PAD + t0 + i] = p.y + bb;
            }
        }
    }
    __syncthreads();

    {
        float a3[4] = {0.f, 0.f, 0.f, 0.f};
#pragma unroll 4
        for (int k = 0; k < NH; ++k) {
            float w = gluw[k * 32 + lane];
            a3[0] += bsh[k * PAD + t0 + 0] * w;
            a3[1] += bsh[k * PAD + t0 + 1] * w;
            a3[2] += bsh[k * PAD + t0 + 2] * w;
            a3[3] += bsh[k * PAD + t0 + 3] * w;
        }
        float gb = glub[lane];
#pragma unroll
        for (int i = 0; i < 4; ++i)
            gsh[(t0 + i) * 32 + lane] = a3[i] + gb;
    }
    __syncthreads();

    if (tid < TT) {
        int t = tid;
        float h[NV];
        float mu = 0.f;
#pragma unroll
        for (int v = 0; v < NV; ++v) {
            float a  = gsh[t * 32 + v];
            float bb = gsh[t * 32 + 16 + v];
            h[v] = a * sigm_f(bb) + rsh[t * 16 + v];
            mu += h[v];
        }
        mu *= (1.f / 16.f);
        float var = 0.f;
#pragma unroll
        for (int v = 0; v < NV; ++v) { float d = h[v] - mu; var += d * d; }
        var *= (1.f / 16.f);
        float rstd = rsqrtf(var + 1e-5f);
        float y[NV], m = -1e30f;
#pragma unroll
        for (int v = 0; v < NV; ++v) {
            y[v] = (h[v] - mu) * rstd * lng[v] + lnb[v];
            m = fmaxf(m, y[v]);
        }
        float s = 0.f;
#pragma unroll
        for (int v = 0; v < NV; ++v) { y[v] = __expf(y[v] - m); s += y[v]; }
        float inv = 1.f / s;
#pragma unroll
        for (int v = 0; v < NV; ++v)
            outw[(n0 + t) * NV + v] = y[v] * inv;
    }
}

// ---------------------------------------------------------------------------
// Kernel 2a: h1 = elu(x @ fc1 + b1), res = x @ skip + bs   (K = 64)
// ---------------------------------------------------------------------------
__global__ __launch_bounds__(256, 2)
void fc1skip_t(const float* __restrict__ fc1b, const float* __restrict__ skb)
{
    GDECL_T;
    const float* A = g_xT + (size_t)v * ND * NTOK + n0;

    GZERO_T();
    GRUN_T(A, g_wf_fc1 + (size_t)v * 8 * 4096, 4096, ND);
    GEPI_T(g_h1 + (size_t)v * NH * NTOK, fc1b + v * NH, elu_f);

    GZERO_T();
    GRUN_T(A, g_wf_sk + (size_t)v * 8 * 4096, 4096, ND);
    GEPI_T(g_res + (size_t)v * NH * NTOK, skb + v * NH, idf);
}

// ---------------------------------------------------------------------------
// Kernel 2b: h2 = h1 @ fc2 + b2   (K = 256)
// ---------------------------------------------------------------------------
__global__ __launch_bounds__(256, 2)
void fc2_t(const float* __restrict__ fc2b)
{
    GDECL_T;
    const float* A = g_h1 + (size_t)v * NH * NTOK + n0;

    GZERO_T();
    GRUN_T(A, g_wf_fc2 + (size_t)v * 32 * 4096, 4096, NH);
    GEPI_T(g_h2 + (size_t)v * NH * NTOK, fc2b + v * NH, idf);
}

// ---------------------------------------------------------------------------
// Kernel 2c-1: a-half of GLU -> g_a   (K = 256)
// ---------------------------------------------------------------------------
__global__ __launch_bounds__(256, 2)
void glu_a_t(const float* __restrict__ glub)
{
    GDECL_T;
    const float* A = g_h2 + (size_t)v * NH * NTOK + n0;

    GZERO_T();
    GRUN_T(A, g_wf_glu + (size_t)v * 32 * 8192, 8192, NH);
    GEPI_T(g_a + (size_t)v * NH * NTOK, glub + v * 512, idf);
}

// ---------------------------------------------------------------------------
// Kernel 2c-2: b-half + hv = a * sigm(b) + res -> g_hv [n][v][c]
// ---------------------------------------------------------------------------
__global__ __launch_bounds__(256, 2)
void glu_b_t(const float* __restrict__ glub)
{
    GDECL_T;
    const float* A = g_h2 + (size_t)v * NH * NTOK + n0;

    GZERO_T();
    GRUN_T(A, g_wf_glu + (size_t)v * 32 * 8192 + 4096, 8192, NH);

    TEPI_SM();

    // pass 1: b + bias -> sigmoid combine with a/res (coalesced over tokens)
    for (int cb = 0; cb < 32; ++cb) {
        int col = warp + cb * 8;
        float bb = glub[v * 512 + 256 + col];
        const float* ap = g_a   + ((size_t)v * NH + col) * NTOK + n0;
        const float* rp = g_res + ((size_t)v * NH + col) * NTOK + n0;
        float b0 = smem[col * 68 + lane] + bb;
        float b1 = smem[col * 68 + 32 + lane] + bb;
        smem[col * 68 + lane]      = ap[lane]      * sigm_f(b0) + rp[lane];
        smem[col * 68 + 32 + lane] = ap[32 + lane] * sigm_f(b1) + rp[32 + lane];
    }
    __syncthreads();

    // pass 2: write hv to g_hv[n][v][c] as float4 over cols
    {
        int tok = tid >> 2, cq = tid & 3;
#pragma unroll
        for (int j = 0; j < 16; ++j) {
            int c4 = (j * 4 + cq) * 4;
            float4 o = make_float4(smem[(c4 + 0) * 68 + tok],
                                   smem[(c4 + 1) * 68 + tok],
                                   smem[(c4 + 2) * 68 + tok],
                                   smem[(c4 + 3) * 68 + tok]);
            *(float4*)(g_hv + (size_t)(n0 + tok) * (NV * NH) + (size_t)v * NH + c4) = o;
        }
    }
}

// ---------------------------------------------------------------------------
// Kernel 3: per-token LN(256) per v + weight scale + sum over v -> selected
// ---------------------------------------------------------------------------
__global__ void combine_kernel(const float* __restrict__ lng, const float* __restrict__ lnb,
                               const float* __restrict__ wts, float* __restrict__ out_sel)
{
    __shared__ float s_part[8 * 260];
    const int n = blockIdx.x;
    const int tid = threadIdx.x;
    const int w = tid >> 5, lane = tid & 31;

    float psum[8];
#pragma unroll
    for (int j = 0; j < 8; ++j) psum[j] = 0.f;

#pragma unroll
    for (int vv = 0; vv < 2; ++vv) {
        int v = w * 2 + vv;
        const float* p = g_hv + (size_t)n * (NV * NH) + v * NH + lane * 8;
        float4 u0 = *(const float4*)p, u1 = *(const float4*)(p + 4);
        float uu[8] = {u0.x, u0.y, u0.z, u0.w, u1.x, u1.y, u1.z, u1.w};
        float s = 0.f, s2 = 0.f;
#pragma unroll
        for (int j = 0; j < 8; ++j) { s += uu[j]; s2 += uu[j] * uu[j]; }
#pragma unroll
        for (int off = 16; off > 0; off >>= 1) {
            s  += __shfl_xor_sync(0xffffffffu, s,  off);
            s2 += __shfl_xor_sync(0xffffffffu, s2, off);
        }
        float mu   = s * (1.f / 256.f);
        float var  = s2 * (1.f / 256.f) - mu * mu;
        float rstd = rsqrtf(var + 1e-5f);
        float wv = wts[n * NV + v];
#pragma unroll
        for (int j = 0; j < 8; ++j) {
            int c = lane * 8 + j;
            float y = (uu[j] - mu) * rstd * lng[v * NH + c] + lnb[v * NH + c];
            psum[j] += y * wv;
        }
    }

    *(float4*)(s_part + w * 260 + lane * 8)     = make_float4(psum[0], psum[1], psum[2], psum[3]);
    *(float4*)(s_part + w * 260 + lane * 8 + 4) = make_float4(psum[4], psum[5], psum[6], psum[7]);
    __syncthreads();

    float s = 0.f;
#pragma unroll
    for (int w8 = 0; w8 < 8; ++w8) s += s_part[w8 * 260 + tid];
    out_sel[(size_t)n * NH + tid] = s;
}

// ---------------------------------------------------------------------------
extern "C" void kernel_launch(void* const* d_in, const int* in_sizes, int n_in,
                              void* d_out, int out_size)
{
    const float* x        = (const float*)d_in[0];
    const float* context  = (const float*)d_in[1];
    const float* vg_fc1_w = (const float*)d_in[2];
    const float* vg_fc1_b = (const float*)d_in[3];
    const float* vg_fc2_w = (const float*)d_in[4];
    const float* vg_fc2_b = (const float*)d_in[5];
    const float* vg_glu_w = (const float*)d_in[6];
    const float* vg_glu_b = (const float*)d_in[7];
    const float* vg_skip_w= (const float*)d_in[8];
    const float* vg_skip_b= (const float*)d_in[9];
    const float* vg_ln_g  = (const float*)d_in[10];
    const float* vg_ln_b  = (const float*)d_in[11];
    const float* wg_fc1_w = (const float*)d_in[12];
    const float* wg_fc1_b = (const float*)d_in[13];
    const float* wg_ctx_w = (const float*)d_in[14];
    const float* wg_fc2_w = (const float*)d_in[15];
    const float* wg_fc2_b = (const float*)d_in[16];
    const float* wg_glu_w = (const float*)d_in[17];
    const float* wg_glu_b = (const float*)d_in[18];
    const float* wg_skip_w= (const float*)d_in[19];
    const float* wg_skip_b= (const float*)d_in[20];
    const float* wg_ln_g  = (const float*)d_in[21];
    const float* wg_ln_b  = (const float*)d_in[22];

    float* out      = (float*)d_out;
    float* out_sel  = out;
    float* out_wts  = out + (size_t)NTOK * NH;

    const int WG_SMEM = (128 * PAD + 2 * 256 * PAD + 64 * 16 + 64 * 32) * 4;
    cudaFuncSetAttribute(wg_kernel, cudaFuncAttributeMaxDynamicSharedMemorySize, WG_SMEM);
    cudaFuncSetAttribute(fc1skip_t, cudaFuncAttributeMaxDynamicSharedMemorySize, G_SMEM_T);
    cudaFuncSetAttribute(fc2_t,     cudaFuncAttributeMaxDynamicSharedMemorySize, G_SMEM_T);
    cudaFuncSetAttribute(glu_a_t,   cudaFuncAttributeMaxDynamicSharedMemorySize, G_SMEM_T);
    cudaFuncSetAttribute(glu_b_t,   cudaFuncAttributeMaxDynamicSharedMemorySize, G_SMEM_T);

    const dim3 xgrid(NTOK / GT, NV);
    const dim3 ggrid(NTOK / GTOK, NV);

    // weight prep (frag-linear tf32 hi/lo)
    wprep<<<dim3(32,  NV), 256>>>(vg_fc1_w,  64,  256, 0);
    wprep<<<dim3(32,  NV), 256>>>(vg_skip_w, 64,  256, 1);
    wprep<<<dim3(128, NV), 256>>>(vg_fc2_w,  256, 256, 2);
    wprep<<<dim3(256, NV), 256>>>(vg_glu_w,  256, 512, 3);

    ctx_kernel<<<32, NH>>>(context, wg_ctx_w);
    xt_kernel<<<xgrid, 256>>>(x);
    wg_kernel<<<NTOK / TT, NTH, WG_SMEM>>>(
        x, wg_fc1_w, wg_fc1_b, wg_fc2_w, wg_fc2_b,
        wg_glu_w, wg_glu_b, wg_skip_w, wg_skip_b, wg_ln_g, wg_ln_b, out_wts);

    fc1skip_t<<<ggrid, 256, G_SMEM_T>>>(vg_fc1_b, vg_skip_b);
    fc2_t<<<ggrid, 256, G_SMEM_T>>>(vg_fc2_b);
    glu_a_t<<<ggrid, 256, G_SMEM_T>>>(vg_glu_b);
    glu_b_t<<<ggrid, 256, G_SMEM_T>>>(vg_glu_b);

    combine_kernel<<<NTOK, 256>>>(vg_ln_g, vg_ln_b, out_wts, out_sel);
}

// round 11
// speedup vs baseline: 1.0136x; 1.0136x over previous
#include <cuda_runtime.h>
#include <math.h>
#include <stdint.h>

// Problem constants
#define NTH   512
#define PAD   65
#define NV    16
#define ND    64
#define NH    256
#define NC    128
#define NTOK  8192
#define TT    64     // wg token tile
#define GT    128    // xt token tile
#define GTOK  64     // gemm token tile
#define BK    16     // gemm k-chunk (2 mma k-steps)
#define NS    3      // pipeline stages
#define SP    132    // xt smem pad
#define TX    68     // xs row stride (pad)

typedef unsigned long long u64;

// Scratch (device globals: allocation-free rule)
__device__ float g_ctxp[32 * NH];
__device__ float g_xT[NV * ND * NTOK];        // x transposed [v][d][n]
__device__ float g_h1[NV * NH * NTOK];        // elu(fc1) [v][c][n]
__device__ float g_res[NV * NH * NTOK];       // skip residual [v][c][n]
__device__ float g_h2[NV * NH * NTOK];        // fc2 out [v][c][n]
__device__ float g_a[NV * NH * NTOK];         // glu a-half [v][c][n]
__device__ float g_hv[NTOK * NV * NH];        // raw hv (pre-LN) [n][v][c]

// Pre-split, fragment-linear tf32 weights: [v][kstep][tile][lane]{hi0,hi1,lo0,lo1}
__device__ float g_wf_fc1[16 * 8  * 4096];    // fc1:  K=64,  N=256
__device__ float g_wf_sk [16 * 8  * 4096];    // skip: K=64,  N=256
__device__ float g_wf_fc2[16 * 32 * 4096];    // fc2:  K=256, N=256
__device__ float g_wf_glu[16 * 32 * 8192];    // glu:  K=256, N=512

__device__ __forceinline__ float elu_f(float x)  { return x > 0.f ? x : (__expf(x) - 1.f); }
__device__ __forceinline__ float sigm_f(float x) { return 1.f / (1.f + __expf(-x)); }
__device__ __forceinline__ float idf(float x)    { return x; }

// ---- 3xTF32 split ----
__device__ __forceinline__ void split_tf32(float x, unsigned& hi, unsigned& lo) {
    asm("cvt.rna.tf32.f32 %0, %1;" : "=r"(hi) : "f"(x));
    float l = x - __uint_as_float(hi);
    asm("cvt.rna.tf32.f32 %0, %1;" : "=r"(lo) : "f"(l));
}

#define MMA_T(D, A0, A1, A2, A3, B0, B1) \
    asm volatile("mma.sync.aligned.m16n8k8.row.col.f32.tf32.tf32.f32 " \
        "{%0,%1,%2,%3}, {%4,%5,%6,%7}, {%8,%9}, {%0,%1,%2,%3};" \
        : "+f"((D)[0]), "+f"((D)[1]), "+f"((D)[2]), "+f"((D)[3]) \
        : "r"(A0), "r"(A1), "r"(A2), "r"(A3), "r"(B0), "r"(B1))

// ---- packed fp32x2 helpers (wg kernel) ----
__device__ __forceinline__ u64 pk2(float a, float b) {
    u64 r; asm("mov.b64 %0, {%1, %2};" : "=l"(r) : "f"(a), "f"(b)); return r;
}
__device__ __forceinline__ void fm2(u64& d, u64 a, u64 b) {
    asm("fma.rn.f32x2 %0, %1, %2, %0;" : "+l"(d) : "l"(a), "l"(b));
}
__device__ __forceinline__ float2 up2(u64 v) {
    float2 f; asm("mov.b64 {%0, %1}, %2;" : "=f"(f.x), "=f"(f.y) : "l"(v)); return f;
}

// ---- cp.async helpers ----
__device__ __forceinline__ void cpa16(unsigned int s, const void* g) {
    asm volatile("cp.async.cg.shared.global [%0], [%1], 16;" :: "r"(s), "l"(g));
}
#define CPA_COMMIT() asm volatile("cp.async.commit_group;" ::: "memory")
#define CPA_WAIT(n)  asm volatile("cp.async.wait_group %0;" :: "n"(n) : "memory")

// ===========================================================================
// Tensor GEMM core v2: block = 64 tokens x 256 cols, 256 threads (8 warps),
// 2 blocks/SM. Warp = 32 tokens x 64 cols = 2 m-tiles x 8 n-tiles (3xTF32).
// One weight float4 feeds 6 MMAs (2 m-tiles) -> halved LDS redundancy.
// smem: NS stages of xs[BK][TX] (raw x) + ws[2][4096] frag weights.
// ===========================================================================
#define G_SMEM_T ((NS * BK * TX + NS * 8192) * 4)   // 111360 B

#define GDECL_T \
    extern __shared__ float smem[]; \
    float* xs = smem; \
    float* ws = smem + NS * BK * TX; \
    const unsigned int xs_u = (unsigned int)__cvta_generic_to_shared(xs); \
    const unsigned int ws_u = (unsigned int)__cvta_generic_to_shared(ws); \
    const int tid  = threadIdx.x; \
    const int lane = tid & 31, warp = tid >> 5; \
    const int kq   = lane & 3,  lq   = lane >> 2; \
    const int ch   = warp & 3; \
    const int tok0 = (warp >> 2) * 32; \
    const int v    = blockIdx.y; \
    const int n0   = blockIdx.x * GTOK; \
    float d[16][4];

#define GZERO_T() do { \
    _Pragma("unroll") for (int _t = 0; _t < 16; ++_t) \
    _Pragma("unroll") for (int _i = 0; _i < 4; ++_i) d[_t][_i] = 0.f; \
} while (0)

// x: 16 rows x 64 floats; w frags: 2 ksteps x 4096 floats (contiguous gmem)
#define ISSUE_T(APTR, WFP, WSTEP_, kc, buf) do { \
    { int kr = tid >> 4, cc2 = tid & 15; \
      cpa16(xs_u + (((buf) * BK + kr) * TX + cc2 * 4) * 4, \
            (APTR) + (size_t)((kc) * BK + kr) * NTOK + cc2 * 4); } \
    _Pragma("unroll") \
    for (int jj = 0; jj < 2; ++jj) { \
      _Pragma("unroll") \
      for (int ii = 0; ii < 4; ++ii) { \
        int off = ii * 1024 + tid * 4; \
        cpa16(ws_u + (((buf) * 2 + jj) * 4096 + off) * 4, \
              (WFP) + (size_t)(2 * (kc) + jj) * (WSTEP_) + off); } } \
} while (0)

#define GCHUNK_T(buf) do { \
    const float* xb = xs + (buf) * BK * TX; \
    _Pragma("unroll") \
    for (int ks = 0; ks < 2; ++ks) { \
        unsigned ah[2][4], al[2][4]; \
        _Pragma("unroll") \
        for (int mt = 0; mt < 2; ++mt) { \
            int tb = tok0 + mt * 16 + lq; \
            float r0 = xb[(ks * 8 + kq) * TX + tb]; \
            float r1 = xb[(ks * 8 + kq) * TX + tb + 8]; \
            float r2 = xb[(ks * 8 + kq + 4) * TX + tb]; \
            float r3 = xb[(ks * 8 + kq + 4) * TX + tb + 8]; \
            split_tf32(r0, ah[mt][0], al[mt][0]); \
            split_tf32(r1, ah[mt][1], al[mt][1]); \
            split_tf32(r2, ah[mt][2], al[mt][2]); \
            split_tf32(r3, ah[mt][3], al[mt][3]); \
        } \
        const float4* wk = reinterpret_cast<const float4*>( \
            ws + ((buf) * 2 + ks) * 4096 + ch * 1024) + lane; \
        _Pragma("unroll") \
        for (int t = 0; t < 8; ++t) { \
            float4 bf = wk[t * 32]; \
            unsigned bh0 = __float_as_uint(bf.x), bh1 = __float_as_uint(bf.y); \
            unsigned bl0 = __float_as_uint(bf.z), bl1 = __float_as_uint(bf.w); \
            _Pragma("unroll") \
            for (int mt = 0; mt < 2; ++mt) { \
                MMA_T(d[mt * 8 + t], ah[mt][0], ah[mt][1], ah[mt][2], ah[mt][3], bh0, bh1); \
                MMA_T(d[mt * 8 + t], ah[mt][0], ah[mt][1], ah[mt][2], ah[mt][3], bl0, bl1); \
                MMA_T(d[mt * 8 + t], al[mt][0], al[mt][1], al[mt][2], al[mt][3], bh0, bh1); \
            } \
        } \
    } \
} while (0)

#define GRUN_T(APTR, WFP, WSTEP_, KN) do { \
    const int nkc = (KN) / BK; \
    _Pragma("unroll") \
    for (int p = 0; p < NS - 1; ++p) { \
        if (p < nkc) { ISSUE_T(APTR, WFP, WSTEP_, p, p); CPA_COMMIT(); } \
    } \
    for (int kc = 0; kc < nkc; ++kc) { \
        CPA_WAIT(NS - 2); \
        __syncthreads(); \
        if (kc + NS - 1 < nkc) { \
            ISSUE_T(APTR, WFP, WSTEP_, kc + NS - 1, (kc + NS - 1) % NS); \
            CPA_COMMIT(); \
        } \
        GCHUNK_T(kc % NS); \
    } \
} while (0)

// Transpose accumulators into smem [col][68] (conflict-free STS)
#define TEPI_SM() do { \
    __syncthreads(); \
    _Pragma("unroll") \
    for (int mt = 0; mt < 2; ++mt) { \
        _Pragma("unroll") \
        for (int t = 0; t < 8; ++t) { \
            int cc = ch * 64 + t * 8 + 2 * kq; \
            int tr = tok0 + mt * 16 + lq; \
            smem[cc * 68 + tr]           = d[mt * 8 + t][0]; \
            smem[(cc + 1) * 68 + tr]     = d[mt * 8 + t][1]; \
            smem[cc * 68 + tr + 8]       = d[mt * 8 + t][2]; \
            smem[(cc + 1) * 68 + tr + 8] = d[mt * 8 + t][3]; \
        } \
    } \
    __syncthreads(); \
} while (0)

// Epilogue: bias + OP, coalesced store to [c][NTOK]
#define GEPI_T(OUTP, BIASP, OP) do { \
    TEPI_SM(); \
    for (int cb = 0; cb < 32; ++cb) { \
        int col = warp + cb * 8; \
        float bb = (BIASP)[col]; \
        float* dp = (OUTP) + (size_t)col * NTOK + n0; \
        dp[lane]      = OP(smem[col * 68 + lane] + bb); \
        dp[32 + lane] = OP(smem[col * 68 + 32 + lane] + bb); \
    } \
    __syncthreads(); \
} while (0)

// ---------------------------------------------------------------------------
// Weight prep: split to tf32 hi/lo, fragment-linear layout.
// sel: 0=fc1, 1=skip, 2=fc2, 3=glu
// ---------------------------------------------------------------------------
__global__ void wprep(const float* __restrict__ W, int K, int N, int sel)
{
    float* F = (sel == 0) ? g_wf_fc1 : (sel == 1) ? g_wf_sk :
               (sel == 2) ? g_wf_fc2 : g_wf_glu;
    const int T = N / 8;
    const int total = (K / 8) * T * 32;
    int idx = blockIdx.x * 256 + threadIdx.x;
    if (idx >= total) return;
    int lane = idx & 31;
    int rest = idx >> 5;
    int t = rest % T, s = rest / T;
    int kq = lane & 3, lq = lane >> 2;
    const float* Wv = W + (size_t)blockIdx.y * K * N;
    float w0 = Wv[(size_t)(s * 8 + kq) * N + t * 8 + lq];
    float w1 = Wv[(size_t)(s * 8 + kq + 4) * N + t * 8 + lq];
    unsigned h0, l0, h1, l1;
    split_tf32(w0, h0, l0);
    split_tf32(w1, h1, l1);
    float4 o = make_float4(__uint_as_float(h0), __uint_as_float(h1),
                           __uint_as_float(l0), __uint_as_float(l1));
    *(float4*)(F + ((size_t)blockIdx.y * total + idx) * 4) = o;
}

// ---------------------------------------------------------------------------
// Kernel 0: context projection
// ---------------------------------------------------------------------------
__global__ void ctx_kernel(const float* __restrict__ ctx, const float* __restrict__ wctx)
{
    int b = blockIdx.x;
    int h = threadIdx.x;
    float acc = 0.f;
    for (int c = 0; c < NC; ++c)
        acc += ctx[b * NC + c] * wctx[c * NH + h];
    g_ctxp[b * NH + h] = acc;
}

// ---------------------------------------------------------------------------
// Kernel: transpose x[n][v][d] -> g_xT[v][d][n]
// ---------------------------------------------------------------------------
__global__ void xt_kernel(const float* __restrict__ x)
{
    __shared__ float s[64 * SP];
    const int v  = blockIdx.y;
    const int n0 = blockIdx.x * GT;
    const int tid = threadIdx.x;

#pragma unroll
    for (int r = 0; r < 8; ++r) {
        int idx = tid + r * 256;
        int t  = idx >> 4;
        int dq = idx & 15;
        float4 val = *(const float4*)(x + (size_t)(n0 + t) * 1024 + v * 64 + dq * 4);
        s[(dq * 4 + 0) * SP + t] = val.x;
        s[(dq * 4 + 1) * SP + t] = val.y;
        s[(dq * 4 + 2) * SP + t] = val.z;
        s[(dq * 4 + 3) * SP + t] = val.w;
    }
    __syncthreads();
#pragma unroll
    for (int r = 0; r < 8; ++r) {
        int idx = tid + r * 256;
        int d  = idx >> 5;
        int tq = idx & 31;
        float4 o = *(const float4*)(s + d * SP + tq * 4);
        *(float4*)(g_xT + ((size_t)v * ND + d) * NTOK + n0 + tq * 4) = o;
    }
}

// ---------------------------------------------------------------------------
// Kernel 1: weight GRN -> softmax weights (FFMA2 path, unchanged)
// ---------------------------------------------------------------------------
#define GSTEP(ACC) do { \
    u64 _xp; \
    _xp = pk2(xs0, xs0); fm2(ACC[0][0], wA.x, _xp); fm2(ACC[0][1], wA.y, _xp); fm2(ACC[0][2], wB.x, _xp); fm2(ACC[0][3], wB.y, _xp); \
    _xp = pk2(xs1, xs1); fm2(ACC[1][0], wA.x, _xp); fm2(ACC[1][1], wA.y, _xp); fm2(ACC[1][2], wB.x, _xp); fm2(ACC[1][3], wB.y, _xp); \
    _xp = pk2(xs2, xs2); fm2(ACC[2][0], wA.x, _xp); fm2(ACC[2][1], wA.y, _xp); fm2(ACC[2][2], wB.x, _xp); fm2(ACC[2][3], wB.y, _xp); \
    _xp = pk2(xs3, xs3); fm2(ACC[3][0], wA.x, _xp); fm2(ACC[3][1], wA.y, _xp); fm2(ACC[3][2], wB.x, _xp); fm2(ACC[3][3], wB.y, _xp); \
} while (0)

#define ZERO44(ACC) do { \
    _Pragma("unroll") for (int _i = 0; _i < 4; ++_i) \
    _Pragma("unroll") for (int _j = 0; _j < 4; ++_j) ACC[_i][_j] = 0ull; \
} while (0)

__global__ __launch_bounds__(NTH, 1)
void wg_kernel(const float* __restrict__ x,
               const float* __restrict__ fc1w, const float* __restrict__ fc1b,
               const float* __restrict__ fc2w, const float* __restrict__ fc2b,
               const float* __restrict__ gluw, const float* __restrict__ glub,
               const float* __restrict__ skw,  const float* __restrict__ skb,
               const float* __restrict__ lng,  const float* __restrict__ lnb,
               float* __restrict__ outw)
{
    extern __shared__ float sm[];
    float* sx  = sm;                       // [128][PAD]
    float* ash = sx  + 128 * PAD;          // [256][PAD]
    float* bsh = ash + 256 * PAD;          // [256][PAD]
    float* rsh = bsh + 256 * PAD;          // [64][16]
    float* gsh = rsh + 64 * 16;            // [64][32]

    const int tid  = threadIdx.x;
    const int warp = tid >> 5, lane = tid & 31;
    const int t0 = warp * 4;
    const int c0 = lane * 8;
    const int n0 = blockIdx.x * TT;
    const int tR = tid >> 3, jR = tid & 7;

    u64 acc[4][4];
    ZERO44(acc);
    float r0 = 0.f, r1 = 0.f;

    for (int kt = 0; kt < 8; ++kt) {
        for (int i = tid; i < TT * 128; i += NTH) {
            int t = i >> 7, k = i & 127;
            sx[k * PAD + t] = x[(size_t)(n0 + t) * 1024 + kt * 128 + k];
        }
        __syncthreads();
        const float* W = fc1w + (size_t)(kt * 128) * NH + c0;
#pragma unroll 2
        for (int k = 0; k < 128; ++k) {
            ulonglong2 wA = *(const ulonglong2*)(W + (size_t)k * NH);
            ulonglong2 wB = *(const ulonglong2*)(W + (size_t)k * NH + 4);
            float xs0 = sx[k * PAD + t0 + 0];
            float xs1 = sx[k * PAD + t0 + 1];
            float xs2 = sx[k * PAD + t0 + 2];
            float xs3 = sx[k * PAD + t0 + 3];
            GSTEP(acc);
        }
        const float* Ws = skw + (size_t)(kt * 128) * NV;
#pragma unroll 4
        for (int k = 0; k < 128; ++k) {
            float xv = sx[k * PAD + tR];
            r0 += xv * Ws[k * NV + jR];
            r1 += xv * Ws[k * NV + jR + 8];
        }
        __syncthreads();
    }

    {
        const int b = n0 >> 8;
#pragma unroll
        for (int j = 0; j < 4; ++j) {
            int ca = c0 + 2 * j, cb = ca + 1;
            float ba = fc1b[ca] + g_ctxp[b * NH + ca];
            float bb = fc1b[cb] + g_ctxp[b * NH + cb];
#pragma unroll
            for (int i = 0; i < 4; ++i) {
                float2 p = up2(acc[i][j]);
                ash[ca * PAD + t0 + i] = elu_f(p.x + ba);
                ash[cb * PAD + t0 + i] = elu_f(p.y + bb);
            }
        }
        rsh[tR * 16 + jR]     = r0 + skb[jR];
        rsh[tR * 16 + jR + 8] = r1 + skb[jR + 8];
    }
    __syncthreads();

    ZERO44(acc);
    {
        const float* W2 = fc2w + c0;
#pragma unroll 2
        for (int k = 0; k < NH; ++k) {
            ulonglong2 wA = *(const ulonglong2*)(W2 + (size_t)k * NH);
            ulonglong2 wB = *(const ulonglong2*)(W2 + (size_t)k * NH + 4);
            float xs0 = ash[k * PAD + t0 + 0];
            float xs1 = ash[k * PAD + t0 + 1];
            float xs2 = ash[k * PAD + t0 + 2];
            float xs3 = ash[k * PAD + t0 + 3];
            GSTEP(acc);
        }
#pragma unroll
        for (int j = 0; j < 4; ++j) {
            int ca = c0 + 2 * j, cb = ca + 1;
            float ba = fc2b[ca], bb = fc2b[cb];
#pragma unroll
            for (int i = 0; i < 4; ++i) {
                float2 p = up2(acc[i][j]);
                bsh[ca * PAD + t0 + i] = p.x + ba;
                bsh[cb * PAD + t0 + i] = p.y + bb;
            }
        }
    }
    __syncthreads();

    {
        float a3[4] = {0.f, 0.f, 0.f, 0.f};
#pragma unroll 4
        for (int k = 0; k < NH; ++k) {
            float w = gluw[k * 32 + lane];
            a3[0] += bsh[k * PAD + t0 + 0] * w;
            a3[1] += bsh[k * PAD + t0 + 1] * w;
            a3[2] += bsh[k * PAD + t0 + 2] * w;
            a3[3] += bsh[k * PAD + t0 + 3] * w;
        }
        float gb = glub[lane];
#pragma unroll
        for (int i = 0; i < 4; ++i)
            gsh[(t0 + i) * 32 + lane] = a3[i] + gb;
    }
    __syncthreads();

    if (tid < TT) {
        int t = tid;
        float h[NV];
        float mu = 0.f;
#pragma unroll
        for (int v = 0; v < NV; ++v) {
            float a  = gsh[t * 32 + v];
            float bb = gsh[t * 32 + 16 + v];
            h[v] = a * sigm_f(bb) + rsh[t * 16 + v];
            mu += h[v];
        }
        mu *= (1.f / 16.f);
        float var = 0.f;
#pragma unroll
        for (int v = 0; v < NV; ++v) { float d = h[v] - mu; var += d * d; }
        var *= (1.f / 16.f);
        float rstd = rsqrtf(var + 1e-5f);
        float y[NV], m = -1e30f;
#pragma unroll
        for (int v = 0; v < NV; ++v) {
            y[v] = (h[v] - mu) * rstd * lng[v] + lnb[v];
            m = fmaxf(m, y[v]);
        }
        float s = 0.f;
#pragma unroll
        for (int v = 0; v < NV; ++v) { y[v] = __expf(y[v] - m); s += y[v]; }
        float inv = 1.f / s;
#pragma unroll
        for (int v = 0; v < NV; ++v)
            outw[(n0 + t) * NV + v] = y[v] * inv;
    }
}

// ---------------------------------------------------------------------------
// Kernel 2a: h1 = elu(x @ fc1 + b1), res = x @ skip + bs   (K = 64)
// ---------------------------------------------------------------------------
__global__ __launch_bounds__(256, 2)
void fc1skip_t(const float* __restrict__ fc1b, const float* __restrict__ skb)
{
    GDECL_T;
    const float* A = g_xT + (size_t)v * ND * NTOK + n0;

    GZERO_T();
    GRUN_T(A, g_wf_fc1 + (size_t)v * 8 * 4096, 4096, ND);
    GEPI_T(g_h1 + (size_t)v * NH * NTOK, fc1b + v * NH, elu_f);

    GZERO_T();
    GRUN_T(A, g_wf_sk + (size_t)v * 8 * 4096, 4096, ND);
    GEPI_T(g_res + (size_t)v * NH * NTOK, skb + v * NH, idf);
}

// ---------------------------------------------------------------------------
// Kernel 2b: h2 = h1 @ fc2 + b2   (K = 256)
// ---------------------------------------------------------------------------
__global__ __launch_bounds__(256, 2)
void fc2_t(const float* __restrict__ fc2b)
{
    GDECL_T;
    const float* A = g_h1 + (size_t)v * NH * NTOK + n0;

    GZERO_T();
    GRUN_T(A, g_wf_fc2 + (size_t)v * 32 * 4096, 4096, NH);
    GEPI_T(g_h2 + (size_t)v * NH * NTOK, fc2b + v * NH, idf);
}

// ---------------------------------------------------------------------------
// Kernel 2c-1: a-half of GLU -> g_a   (K = 256)
// ---------------------------------------------------------------------------
__global__ __launch_bounds__(256, 2)
void glu_a_t(const float* __restrict__ glub)
{
    GDECL_T;
    const float* A = g_h2 + (size_t)v * NH * NTOK + n0;

    GZERO_T();
    GRUN_T(A, g_wf_glu + (size_t)v * 32 * 8192, 8192, NH);
    GEPI_T(g_a + (size_t)v * NH * NTOK, glub + v * 512, idf);
}

// ---------------------------------------------------------------------------
// Kernel 2c-2: b-half + hv = a * sigm(b) + res -> g_hv [n][v][c]
// ---------------------------------------------------------------------------
__global__ __launch_bounds__(256, 2)
void glu_b_t(const float* __restrict__ glub)
{
    GDECL_T;
    const float* A = g_h2 + (size_t)v * NH * NTOK + n0;

    GZERO_T();
    GRUN_T(A, g_wf_glu + (size_t)v * 32 * 8192 + 4096, 8192, NH);

    TEPI_SM();

    // pass 1: b + bias -> sigmoid combine with a/res (coalesced over tokens)
    for (int cb = 0; cb < 32; ++cb) {
        int col = warp + cb * 8;
        float bb = glub[v * 512 + 256 + col];
        const float* ap = g_a   + ((size_t)v * NH + col) * NTOK + n0;
        const float* rp = g_res + ((size_t)v * NH + col) * NTOK + n0;
        float b0 = smem[col * 68 + lane] + bb;
        float b1 = smem[col * 68 + 32 + lane] + bb;
        smem[col * 68 + lane]      = ap[lane]      * sigm_f(b0) + rp[lane];
        smem[col * 68 + 32 + lane] = ap[32 + lane] * sigm_f(b1) + rp[32 + lane];
    }
    __syncthreads();

    // pass 2: write hv to g_hv[n][v][c] as float4 over cols
    {
        int tok = tid >> 2, cq = tid & 3;
#pragma unroll
        for (int j = 0; j < 16; ++j) {
            int c4 = (j * 4 + cq) * 4;
            float4 o = make_float4(smem[(c4 + 0) * 68 + tok],
                                   smem[(c4 + 1) * 68 + tok],
                                   smem[(c4 + 2) * 68 + tok],
                                   smem[(c4 + 3) * 68 + tok]);
            *(float4*)(g_hv + (size_t)(n0 + tok) * (NV * NH) + (size_t)v * NH + c4) = o;
        }
    }
}

// ---------------------------------------------------------------------------
// Kernel 3: per-token LN(256) per v + weight scale + sum over v -> selected
// ---------------------------------------------------------------------------
__global__ void combine_kernel(const float* __restrict__ lng, const float* __restrict__ lnb,
                               const float* __restrict__ wts, float* __restrict__ out_sel)
{
    __shared__ float s_part[8 * 260];
    const int n = blockIdx.x;
    const int tid = threadIdx.x;
    const int w = tid >> 5, lane = tid & 31;

    float psum[8];
#pragma unroll
    for (int j = 0; j < 8; ++j) psum[j] = 0.f;

#pragma unroll
    for (int vv = 0; vv < 2; ++vv) {
        int v = w * 2 + vv;
        const float* p = g_hv + (size_t)n * (NV * NH) + v * NH + lane * 8;
        float4 u0 = *(const float4*)p, u1 = *(const float4*)(p + 4);
        float uu[8] = {u0.x, u0.y, u0.z, u0.w, u1.x, u1.y, u1.z, u1.w};
        float s = 0.f, s2 = 0.f;
#pragma unroll
        for (int j = 0; j < 8; ++j) { s += uu[j]; s2 += uu[j] * uu[j]; }
#pragma unroll
        for (int off = 16; off > 0; off >>= 1) {
            s  += __shfl_xor_sync(0xffffffffu, s,  off);
            s2 += __shfl_xor_sync(0xffffffffu, s2, off);
        }
        float mu   = s * (1.f / 256.f);
        float var  = s2 * (1.f / 256.f) - mu * mu;
        float rstd = rsqrtf(var + 1e-5f);
        float wv = wts[n * NV + v];
#pragma unroll
        for (int j = 0; j < 8; ++j) {
            int c = lane * 8 + j;
            float y = (uu[j] - mu) * rstd * lng[v * NH + c] + lnb[v * NH + c];
            psum[j] += y * wv;
        }
    }

    *(float4*)(s_part + w * 260 + lane * 8)     = make_float4(psum[0], psum[1], psum[2], psum[3]);
    *(float4*)(s_part + w * 260 + lane * 8 + 4) = make_float4(psum[4], psum[5], psum[6], psum[7]);
    __syncthreads();

    float s = 0.f;
#pragma unroll
    for (int w8 = 0; w8 < 8; ++w8) s += s_part[w8 * 260 + tid];
    out_sel[(size_t)n * NH + tid] = s;
}

// ---------------------------------------------------------------------------
extern "C" void kernel_launch(void* const* d_in, const int* in_sizes, int n_in,
                              void* d_out, int out_size)
{
    const float* x        = (const float*)d_in[0];
    const float* context  = (const float*)d_in[1];
    const float* vg_fc1_w = (const float*)d_in[2];
    const float* vg_fc1_b = (const float*)d_in[3];
    const float* vg_fc2_w = (const float*)d_in[4];
    const float* vg_fc2_b = (const float*)d_in[5];
    const float* vg_glu_w = (const float*)d_in[6];
    const float* vg_glu_b = (const float*)d_in[7];
    const float* vg_skip_w= (const float*)d_in[8];
    const float* vg_skip_b= (const float*)d_in[9];
    const float* vg_ln_g  = (const float*)d_in[10];
    const float* vg_ln_b  = (const float*)d_in[11];
    const float* wg_fc1_w = (const float*)d_in[12];
    const float* wg_fc1_b = (const float*)d_in[13];
    const float* wg_ctx_w = (const float*)d_in[14];
    const float* wg_fc2_w = (const float*)d_in[15];
    const float* wg_fc2_b = (const float*)d_in[16];
    const float* wg_glu_w = (const float*)d_in[17];
    const float* wg_glu_b = (const float*)d_in[18];
    const float* wg_skip_w= (const float*)d_in[19];
    const float* wg_skip_b= (const float*)d_in[20];
    const float* wg_ln_g  = (const float*)d_in[21];
    const float* wg_ln_b  = (const float*)d_in[22];

    float* out      = (float*)d_out;
    float* out_sel  = out;
    float* out_wts  = out + (size_t)NTOK * NH;

    const int WG_SMEM = (128 * PAD + 2 * 256 * PAD + 64 * 16 + 64 * 32) * 4;
    cudaFuncSetAttribute(wg_kernel, cudaFuncAttributeMaxDynamicSharedMemorySize, WG_SMEM);
    cudaFuncSetAttribute(fc1skip_t, cudaFuncAttributeMaxDynamicSharedMemorySize, G_SMEM_T);
    cudaFuncSetAttribute(fc2_t,     cudaFuncAttributeMaxDynamicSharedMemorySize, G_SMEM_T);
    cudaFuncSetAttribute(glu_a_t,   cudaFuncAttributeMaxDynamicSharedMemorySize, G_SMEM_T);
    cudaFuncSetAttribute(glu_b_t,   cudaFuncAttributeMaxDynamicSharedMemorySize, G_SMEM_T);

    const dim3 xgrid(NTOK / GT, NV);
    const dim3 ggrid(NTOK / GTOK, NV);

    // weight prep (frag-linear tf32 hi/lo)
    wprep<<<dim3(32,  NV), 256>>>(vg_fc1_w,  64,  256, 0);
    wprep<<<dim3(32,  NV), 256>>>(vg_skip_w, 64,  256, 1);
    wprep<<<dim3(128, NV), 256>>>(vg_fc2_w,  256, 256, 2);
    wprep<<<dim3(256, NV), 256>>>(vg_glu_w,  256, 512, 3);

    ctx_kernel<<<32, NH>>>(context, wg_ctx_w);
    xt_kernel<<<xgrid, 256>>>(x);
    wg_kernel<<<NTOK / TT, NTH, WG_SMEM>>>(
        x, wg_fc1_w, wg_fc1_b, wg_fc2_w, wg_fc2_b,
        wg_glu_w, wg_glu_b, wg_skip_w, wg_skip_b, wg_ln_g, wg_ln_b, out_wts);

    fc1skip_t<<<ggrid, 256, G_SMEM_T>>>(vg_fc1_b, vg_skip_b);
    fc2_t<<<ggrid, 256, G_SMEM_T>>>(vg_fc2_b);
    glu_a_t<<<ggrid, 256, G_SMEM_T>>>(vg_glu_b);
    glu_b_t<<<ggrid, 256, G_SMEM_T>>>(vg_glu_b);

    combine_kernel<<<NTOK, 256>>>(vg_ln_g, vg_ln_b, out_wts, out_sel);
}

// round 12
// speedup vs baseline: 1.1244x; 1.1093x over previous
#include <cuda_runtime.h>
#include <math.h>
#include <stdint.h>

// Problem constants
#define NTH   512
#define PAD   65
#define NV    16
#define ND    64
#define NH    256
#define NC    128
#define NTOK  8192
#define TT    64     // wg token tile
#define GT    128    // xt token tile
#define GTOK  64     // gemm token tile
#define BK    16     // gemm k-chunk
#define NS    4      // pipeline stages
#define SP    132    // xt smem pad

typedef unsigned long long u64;

// Scratch (device globals: allocation-free rule)
__device__ float g_ctxp[32 * NH];
__device__ float g_xT[NV * ND * NTOK];        // x transposed [v][d][n] == flat^T [k][n]
__device__ float g_h1[NV * NH * NTOK];        // elu(fc1) [v][c][n]
__device__ float g_res[NV * NH * NTOK];       // skip residual [v][c][n]
__device__ float g_h2[NV * NH * NTOK];        // fc2 out [v][c][n]
__device__ float g_a[NV * NH * NTOK];         // glu a-half [v][c][n]
__device__ float g_hv[NTOK * NV * NH];        // raw hv (pre-LN) [n][v][c]
__device__ float g_wh1[NH * NTOK];            // wg h1 (post elu+ctx) [c][n]

__device__ __forceinline__ float elu_f(float x)  { return x > 0.f ? x : (__expf(x) - 1.f); }
__device__ __forceinline__ float sigm_f(float x) { return 1.f / (1.f + __expf(-x)); }
__device__ __forceinline__ float idf(float x)    { return x; }

// ---- packed fp32x2 helpers ----
__device__ __forceinline__ u64 pk2(float a, float b) {
    u64 r; asm("mov.b64 %0, {%1, %2};" : "=l"(r) : "f"(a), "f"(b)); return r;
}
__device__ __forceinline__ void fm2(u64& d, u64 a, u64 b) {
    asm("fma.rn.f32x2 %0, %1, %2, %0;" : "+l"(d) : "l"(a), "l"(b));
}
__device__ __forceinline__ float2 up2(u64 v) {
    float2 f; asm("mov.b64 {%0, %1}, %2;" : "=f"(f.x), "=f"(f.y) : "l"(v)); return f;
}

// ---- cp.async helpers ----
__device__ __forceinline__ void cpa16(unsigned int s, const void* g) {
    asm volatile("cp.async.cg.shared.global [%0], [%1], 16;" :: "r"(s), "l"(g));
}
#define CPA_COMMIT() asm volatile("cp.async.commit_group;" ::: "memory")
#define CPA_WAIT(n)  asm volatile("cp.async.wait_group %0;" :: "n"(n) : "memory")

// ===========================================================================
// Tiled GEMM core (R8): block = 64 tokens x 256 cols, 256 threads, 2 blocks/SM.
// Thread tile: 8 tokens x 8 cols as two split quads (cA..cA+3, cA+128..cA+131).
// ===========================================================================
#define GDECL \
    extern __shared__ float smem[]; \
    float* xs = smem; \
    float* ws = smem + NS * BK * GTOK; \
    const unsigned int xs_u = (unsigned int)__cvta_generic_to_shared(xs); \
    const unsigned int ws_u = (unsigned int)__cvta_generic_to_shared(ws); \
    const int tid = threadIdx.x; \
    const int t0  = (tid >> 5) * 8; \
    const int cA  = (tid & 31) * 4; \
    const int v   = blockIdx.y; \
    const int n0  = blockIdx.x * GTOK; \
    u64 acc[8][4]; \
    (void)v;

#define GCOL(c) (cA + ((c) & 3) + (((c) >> 2) * 128))

#define GZERO() do { \
    _Pragma("unroll") for (int _c = 0; _c < 8; ++_c) \
    _Pragma("unroll") for (int _t = 0; _t < 4; ++_t) acc[_c][_t] = 0ull; \
} while (0)

#define ISSUE(APTR, WPTR, WS_, k0, buf) do { \
    { int kr = tid >> 4, cc = tid & 15; \
      cpa16(xs_u + (((buf) * BK + kr) * GTOK + cc * 4) * 4, \
            (APTR) + (size_t)((k0) + kr) * NTOK + cc * 4); } \
    _Pragma("unroll") \
    for (int s2 = 0; s2 < 4; ++s2) { \
      int ci = tid + s2 * 256; int kr = ci >> 6, cc = ci & 63; \
      cpa16(ws_u + (((buf) * BK + kr) * NH + cc * 4) * 4, \
            (WPTR) + (size_t)((k0) + kr) * (WS_) + cc * 4); } \
} while (0)

#define GCHUNK(buf) do { \
    const float* xr = xs + (buf) * BK * GTOK + t0; \
    const float* wr = ws + (buf) * BK * NH + cA; \
    _Pragma("unroll") \
    for (int kk = 0; kk < BK; ++kk) { \
        float4 xa = *(const float4*)(xr + kk * GTOK); \
        float4 xb = *(const float4*)(xr + kk * GTOK + 4); \
        float4 wa = *(const float4*)(wr + kk * NH); \
        float4 wb = *(const float4*)(wr + kk * NH + 128); \
        u64 xp0 = pk2(xa.x, xa.y), xp1 = pk2(xa.z, xa.w); \
        u64 xp2 = pk2(xb.x, xb.y), xp3 = pk2(xb.z, xb.w); \
        u64 q; \
        q = pk2(wa.x, wa.x); fm2(acc[0][0], q, xp0); fm2(acc[0][1], q, xp1); fm2(acc[0][2], q, xp2); fm2(acc[0][3], q, xp3); \
        q = pk2(wa.y, wa.y); fm2(acc[1][0], q, xp0); fm2(acc[1][1], q, xp1); fm2(acc[1][2], q, xp2); fm2(acc[1][3], q, xp3); \
        q = pk2(wa.z, wa.z); fm2(acc[2][0], q, xp0); fm2(acc[2][1], q, xp1); fm2(acc[2][2], q, xp2); fm2(acc[2][3], q, xp3); \
        q = pk2(wa.w, wa.w); fm2(acc[3][0], q, xp0); fm2(acc[3][1], q, xp1); fm2(acc[3][2], q, xp2); fm2(acc[3][3], q, xp3); \
        q = pk2(wb.x, wb.x); fm2(acc[4][0], q, xp0); fm2(acc[4][1], q, xp1); fm2(acc[4][2], q, xp2); fm2(acc[4][3], q, xp3); \
        q = pk2(wb.y, wb.y); fm2(acc[5][0], q, xp0); fm2(acc[5][1], q, xp1); fm2(acc[5][2], q, xp2); fm2(acc[5][3], q, xp3); \
        q = pk2(wb.z, wb.z); fm2(acc[6][0], q, xp0); fm2(acc[6][1], q, xp1); fm2(acc[6][2], q, xp2); fm2(acc[6][3], q, xp3); \
        q = pk2(wb.w, wb.w); fm2(acc[7][0], q, xp0); fm2(acc[7][1], q, xp1); fm2(acc[7][2], q, xp2); fm2(acc[7][3], q, xp3); \
    } \
} while (0)

#define GRUN(APTR, WPTR, WS_, KN) do { \
    const int nkc = (KN) / BK; \
    _Pragma("unroll") \
    for (int p = 0; p < NS - 1; ++p) { \
        if (p < nkc) { ISSUE(APTR, WPTR, WS_, p * BK, p); CPA_COMMIT(); } \
    } \
    for (int kc = 0; kc < nkc; ++kc) { \
        CPA_WAIT(NS - 2); \
        __syncthreads(); \
        if (kc + NS - 1 < nkc) { \
            ISSUE(APTR, WPTR, WS_, (kc + NS - 1) * BK, (kc + NS - 1) % NS); \
            CPA_COMMIT(); \
        } \
        GCHUNK(kc % NS); \
    } \
} while (0)

#define GEPI(OUTP, BIASP, OP) do { \
    _Pragma("unroll") \
    for (int c = 0; c < 8; ++c) { \
        int col = GCOL(c); float bb = (BIASP)[col]; \
        float2 p0 = up2(acc[c][0]), p1 = up2(acc[c][1]); \
        float2 p2 = up2(acc[c][2]), p3 = up2(acc[c][3]); \
        float* d = (OUTP) + (size_t)col * NTOK + n0 + t0; \
        *(float4*)d       = make_float4(OP(p0.x + bb), OP(p0.y + bb), OP(p1.x + bb), OP(p1.y + bb)); \
        *(float4*)(d + 4) = make_float4(OP(p2.x + bb), OP(p2.y + bb), OP(p3.x + bb), OP(p3.y + bb)); \
    } \
} while (0)

// ---------------------------------------------------------------------------
// Kernel 0: context projection
// ---------------------------------------------------------------------------
__global__ void ctx_kernel(const float* __restrict__ ctx, const float* __restrict__ wctx)
{
    int b = blockIdx.x;
    int h = threadIdx.x;
    float acc = 0.f;
    for (int c = 0; c < NC; ++c)
        acc += ctx[b * NC + c] * wctx[c * NH + h];
    g_ctxp[b * NH + h] = acc;
}

// ---------------------------------------------------------------------------
// Kernel: transpose x[n][v][d] -> g_xT[v][d][n]
// ---------------------------------------------------------------------------
__global__ void xt_kernel(const float* __restrict__ x)
{
    __shared__ float s[64 * SP];
    const int v  = blockIdx.y;
    const int n0 = blockIdx.x * GT;
    const int tid = threadIdx.x;

#pragma unroll
    for (int r = 0; r < 8; ++r) {
        int idx = tid + r * 256;
        int t  = idx >> 4;
        int dq = idx & 15;
        float4 val = *(const float4*)(x + (size_t)(n0 + t) * 1024 + v * 64 + dq * 4);
        s[(dq * 4 + 0) * SP + t] = val.x;
        s[(dq * 4 + 1) * SP + t] = val.y;
        s[(dq * 4 + 2) * SP + t] = val.z;
        s[(dq * 4 + 3) * SP + t] = val.w;
    }
    __syncthreads();
#pragma unroll
    for (int r = 0; r < 8; ++r) {
        int idx = tid + r * 256;
        int d  = idx >> 5;
        int tq = idx & 31;
        float4 o = *(const float4*)(s + d * SP + tq * 4);
        *(float4*)(g_xT + ((size_t)v * ND + d) * NTOK + n0 + tq * 4) = o;
    }
}

// ---------------------------------------------------------------------------
// Kernel: wg fc1 via pipelined GEMM. A = g_xT [1024][8192], W = wg_fc1_w.
// Epilogue: + fc1b + ctx, elu -> g_wh1[c][n].
// ---------------------------------------------------------------------------
__global__ __launch_bounds__(256, 2)
void wgfc1_kernel(const float* __restrict__ fc1w, const float* __restrict__ fc1b)
{
    GDECL;
    const float* A = g_xT + n0;

    GZERO();
    GRUN(A, fc1w, NH, 1024);

    const int b = n0 >> 8;   // 64 | 256 so block lies in one batch
#pragma unroll
    for (int c = 0; c < 8; ++c) {
        int col = GCOL(c);
        float bb = fc1b[col] + g_ctxp[b * NH + col];
        float2 p0 = up2(acc[c][0]), p1 = up2(acc[c][1]);
        float2 p2 = up2(acc[c][2]), p3 = up2(acc[c][3]);
        float* d = g_wh1 + (size_t)col * NTOK + n0 + t0;
        *(float4*)d       = make_float4(elu_f(p0.x + bb), elu_f(p0.y + bb), elu_f(p1.x + bb), elu_f(p1.y + bb));
        *(float4*)(d + 4) = make_float4(elu_f(p2.x + bb), elu_f(p2.y + bb), elu_f(p3.x + bb), elu_f(p3.y + bb));
    }
}

// ---------------------------------------------------------------------------
// Kernel 1: weight GRN rest: skip residual + fc2 + glu + LN + softmax.
// h1 comes precomputed from g_wh1.
// ---------------------------------------------------------------------------
#define GSTEP(ACC) do { \
    u64 _xp; \
    _xp = pk2(xs0, xs0); fm2(ACC[0][0], wA.x, _xp); fm2(ACC[0][1], wA.y, _xp); fm2(ACC[0][2], wB.x, _xp); fm2(ACC[0][3], wB.y, _xp); \
    _xp = pk2(xs1, xs1); fm2(ACC[1][0], wA.x, _xp); fm2(ACC[1][1], wA.y, _xp); fm2(ACC[1][2], wB.x, _xp); fm2(ACC[1][3], wB.y, _xp); \
    _xp = pk2(xs2, xs2); fm2(ACC[2][0], wA.x, _xp); fm2(ACC[2][1], wA.y, _xp); fm2(ACC[2][2], wB.x, _xp); fm2(ACC[2][3], wB.y, _xp); \
    _xp = pk2(xs3, xs3); fm2(ACC[3][0], wA.x, _xp); fm2(ACC[3][1], wA.y, _xp); fm2(ACC[3][2], wB.x, _xp); fm2(ACC[3][3], wB.y, _xp); \
} while (0)

#define ZERO44(ACC) do { \
    _Pragma("unroll") for (int _i = 0; _i < 4; ++_i) \
    _Pragma("unroll") for (int _j = 0; _j < 4; ++_j) ACC[_i][_j] = 0ull; \
} while (0)

__global__ __launch_bounds__(NTH, 1)
void wg_kernel(const float* __restrict__ x,
               const float* __restrict__ fc2w, const float* __restrict__ fc2b,
               const float* __restrict__ gluw, const float* __restrict__ glub,
               const float* __restrict__ skw,  const float* __restrict__ skb,
               const float* __restrict__ lng,  const float* __restrict__ lnb,
               float* __restrict__ outw)
{
    extern __shared__ float sm[];
    float* sx  = sm;                       // [128][PAD]
    float* ash = sx  + 128 * PAD;          // [256][PAD]  h1 from g_wh1
    float* bsh = ash + 256 * PAD;          // [256][PAD]
    float* rsh = bsh + 256 * PAD;          // [64][16]
    float* gsh = rsh + 64 * 16;            // [64][32]

    const int tid  = threadIdx.x;
    const int warp = tid >> 5, lane = tid & 31;
    const int t0 = warp * 4;
    const int c0 = lane * 8;
    const int n0 = blockIdx.x * TT;
    const int tR = tid >> 3, jR = tid & 7;

    float r0 = 0.f, r1 = 0.f;

    // ---- stage 1: residual = flat @ skip (K=1024, 8 k-tiles) ----
    for (int kt = 0; kt < 8; ++kt) {
        for (int i = tid; i < TT * 128; i += NTH) {
            int t = i >> 7, k = i & 127;
            sx[k * PAD + t] = x[(size_t)(n0 + t) * 1024 + kt * 128 + k];
        }
        __syncthreads();
        const float* Ws = skw + (size_t)(kt * 128) * NV;
#pragma unroll 4
        for (int k = 0; k < 128; ++k) {
            float xv = sx[k * PAD + tR];
            r0 += xv * Ws[k * NV + jR];
            r1 += xv * Ws[k * NV + jR + 8];
        }
        __syncthreads();
    }
    rsh[tR * 16 + jR]     = r0 + skb[jR];
    rsh[tR * 16 + jR + 8] = r1 + skb[jR + 8];

    // ---- stage 1b: load h1 (post elu+ctx) from g_wh1 into ash[c][t] ----
    for (int i = tid; i < 256 * 16; i += NTH) {
        int c = i >> 4, tq = i & 15;
        float4 u = *(const float4*)(g_wh1 + (size_t)c * NTOK + n0 + tq * 4);
        ash[c * PAD + tq * 4 + 0] = u.x;
        ash[c * PAD + tq * 4 + 1] = u.y;
        ash[c * PAD + tq * 4 + 2] = u.z;
        ash[c * PAD + tq * 4 + 3] = u.w;
    }
    __syncthreads();

    // ---- stage 2: h2 = h1 @ fc2 + b2 -> bsh ----
    u64 acc[4][4];
    ZERO44(acc);
    {
        const float* W2 = fc2w + c0;
#pragma unroll 2
        for (int k = 0; k < NH; ++k) {
            ulonglong2 wA = *(const ulonglong2*)(W2 + (size_t)k * NH);
            ulonglong2 wB = *(const ulonglong2*)(W2 + (size_t)k * NH + 4);
            float xs0 = ash[k * PAD + t0 + 0];
            float xs1 = ash[k * PAD + t0 + 1];
            float xs2 = ash[k * PAD + t0 + 2];
            float xs3 = ash[k * PAD + t0 + 3];
            GSTEP(acc);
        }
#pragma unroll
        for (int j = 0; j < 4; ++j) {
            int ca = c0 + 2 * j, cb = ca + 1;
            float ba = fc2b[ca], bb = fc2b[cb];
#pragma unroll
            for (int i = 0; i < 4; ++i) {
                float2 p = up2(acc[i][j]);
                bsh[ca * PAD + t0 + i] = p.x + ba;
                bsh[cb * PAD + t0 + i] = p.y + bb;
            }
        }
    }
    __syncthreads();

    // ---- stage 3: g = h2 @ glu_w + glu_b (K=256, 32 cols) ----
    {
        float a3[4] = {0.f, 0.f, 0.f, 0.f};
#pragma unroll 4
        for (int k = 0; k < NH; ++k) {
            float w = gluw[k * 32 + lane];
            a3[0] += bsh[k * PAD + t0 + 0] * w;
            a3[1] += bsh[k * PAD + t0 + 1] * w;
            a3[2] += bsh[k * PAD + t0 + 2] * w;
            a3[3] += bsh[k * PAD + t0 + 3] * w;
        }
        float gb = glub[lane];
#pragma unroll
        for (int i = 0; i < 4; ++i)
            gsh[(t0 + i) * 32 + lane] = a3[i] + gb;
    }
    __syncthreads();

    // ---- stage 4: GLU + residual + LN(16) + softmax(16) ----
    if (tid < TT) {
        int t = tid;
        float h[NV];
        float mu = 0.f;
#pragma unroll
        for (int v = 0; v < NV; ++v) {
            float a  = gsh[t * 32 + v];
            float bb = gsh[t * 32 + 16 + v];
            h[v] = a * sigm_f(bb) + rsh[t * 16 + v];
            mu += h[v];
        }
        mu *= (1.f / 16.f);
        float var = 0.f;
#pragma unroll
        for (int v = 0; v < NV; ++v) { float d = h[v] - mu; var += d * d; }
        var *= (1.f / 16.f);
        float rstd = rsqrtf(var + 1e-5f);
        float y[NV], m = -1e30f;
#pragma unroll
        for (int v = 0; v < NV; ++v) {
            y[v] = (h[v] - mu) * rstd * lng[v] + lnb[v];
            m = fmaxf(m, y[v]);
        }
        float s = 0.f;
#pragma unroll
        for (int v = 0; v < NV; ++v) { y[v] = __expf(y[v] - m); s += y[v]; }
        float inv = 1.f / s;
#pragma unroll
        for (int v = 0; v < NV; ++v)
            outw[(n0 + t) * NV + v] = y[v] * inv;
    }
}

// ---------------------------------------------------------------------------
// Kernel 2a: h1 = elu(x @ fc1 + b1), res = x @ skip + bs   (K = 64)
// ---------------------------------------------------------------------------
__global__ __launch_bounds__(256, 2)
void fc1skip_kernel(const float* __restrict__ fc1w, const float* __restrict__ fc1b,
                    const float* __restrict__ skw,  const float* __restrict__ skb)
{
    GDECL;
    const float* A  = g_xT + (size_t)v * ND * NTOK + n0;
    const float* W1 = fc1w + (size_t)v * ND * NH;
    const float* W2 = skw  + (size_t)v * ND * NH;

    GZERO();
    GRUN(A, W1, NH, ND);
    GEPI(g_h1 + (size_t)v * NH * NTOK, fc1b + v * NH, elu_f);

    GZERO();
    GRUN(A, W2, NH, ND);
    GEPI(g_res + (size_t)v * NH * NTOK, skb + v * NH, idf);
}

// ---------------------------------------------------------------------------
// Kernel 2b: h2 = h1 @ fc2 + b2   (K = 256)
// ---------------------------------------------------------------------------
__global__ __launch_bounds__(256, 2)
void fc2_kernel(const float* __restrict__ fc2w, const float* __restrict__ fc2b)
{
    GDECL;
    const float* A = g_h1 + (size_t)v * NH * NTOK + n0;
    const float* W = fc2w + (size_t)v * NH * NH;

    GZERO();
    GRUN(A, W, NH, NH);
    GEPI(g_h2 + (size_t)v * NH * NTOK, fc2b + v * NH, idf);
}

// ---------------------------------------------------------------------------
// Kernel 2c-1: a-half of GLU -> g_a   (K = 256)
// ---------------------------------------------------------------------------
__global__ __launch_bounds__(256, 2)
void glu_a_kernel(const float* __restrict__ gluw, const float* __restrict__ glub)
{
    GDECL;
    const float* A = g_h2 + (size_t)v * NH * NTOK + n0;
    const float* W = gluw + (size_t)v * NH * 512;

    GZERO();
    GRUN(A, W, 512, NH);
    GEPI(g_a + (size_t)v * NH * NTOK, glub + v * 512, idf);
}

// ---------------------------------------------------------------------------
// Kernel 2c-2: b-half + combine: hv = a * sigm(b) + res -> g_hv [n][v][c]
// ---------------------------------------------------------------------------
__global__ __launch_bounds__(256, 2)
void glu_b_kernel(const float* __restrict__ gluw, const float* __restrict__ glub)
{
    GDECL;
    const float* A = g_h2 + (size_t)v * NH * NTOK + n0;
    const float* W = gluw + (size_t)v * NH * 512 + 256;

    GZERO();
    GRUN(A, W, 512, NH);

#pragma unroll
    for (int c = 0; c < 8; ++c) {
        int col = GCOL(c);
        float bb = glub[v * 512 + 256 + col];
        const float* ap = g_a   + ((size_t)v * NH + col) * NTOK + n0 + t0;
        const float* rp = g_res + ((size_t)v * NH + col) * NTOK + n0 + t0;
        float4 a0 = *(const float4*)ap, a1 = *(const float4*)(ap + 4);
        float4 r0 = *(const float4*)rp, r1 = *(const float4*)(rp + 4);
        float2 p0 = up2(acc[c][0]), p1 = up2(acc[c][1]);
        float2 p2 = up2(acc[c][2]), p3 = up2(acc[c][3]);
        float h0 = a0.x * sigm_f(p0.x + bb) + r0.x;
        float h1 = a0.y * sigm_f(p0.y + bb) + r0.y;
        float h2 = a0.z * sigm_f(p1.x + bb) + r0.z;
        float h3 = a0.w * sigm_f(p1.y + bb) + r0.w;
        float h4 = a1.x * sigm_f(p2.x + bb) + r1.x;
        float h5 = a1.y * sigm_f(p2.y + bb) + r1.y;
        float h6 = a1.z * sigm_f(p3.x + bb) + r1.z;
        float h7 = a1.w * sigm_f(p3.y + bb) + r1.w;
        acc[c][0] = pk2(h0, h1); acc[c][1] = pk2(h2, h3);
        acc[c][2] = pk2(h4, h5); acc[c][3] = pk2(h6, h7);
    }

#pragma unroll
    for (int tp = 0; tp < 4; ++tp) {
        float2 q0 = up2(acc[0][tp]), q1 = up2(acc[1][tp]);
        float2 q2 = up2(acc[2][tp]), q3 = up2(acc[3][tp]);
        float2 q4 = up2(acc[4][tp]), q5 = up2(acc[5][tp]);
        float2 q6 = up2(acc[6][tp]), q7 = up2(acc[7][tp]);
        float* dA = g_hv + (size_t)(n0 + t0 + 2 * tp)     * (NV * NH) + v * NH;
        float* dB = g_hv + (size_t)(n0 + t0 + 2 * tp + 1) * (NV * NH) + v * NH;
        *(float4*)(dA + cA)       = make_float4(q0.x, q1.x, q2.x, q3.x);
        *(float4*)(dA + cA + 128) = make_float4(q4.x, q5.x, q6.x, q7.x);
        *(float4*)(dB + cA)       = make_float4(q0.y, q1.y, q2.y, q3.y);
        *(float4*)(dB + cA + 128) = make_float4(q4.y, q5.y, q6.y, q7.y);
    }
}

// ---------------------------------------------------------------------------
// Kernel 3: per-token LN(256) per v + weight scale + sum over v -> selected
// ---------------------------------------------------------------------------
__global__ void combine_kernel(const float* __restrict__ lng, const float* __restrict__ lnb,
                               const float* __restrict__ wts, float* __restrict__ out_sel)
{
    __shared__ float s_part[8 * 260];
    const int n = blockIdx.x;
    const int tid = threadIdx.x;
    const int w = tid >> 5, lane = tid & 31;

    float psum[8];
#pragma unroll
    for (int j = 0; j < 8; ++j) psum[j] = 0.f;

#pragma unroll
    for (int vv = 0; vv < 2; ++vv) {
        int v = w * 2 + vv;
        const float* p = g_hv + (size_t)n * (NV * NH) + v * NH + lane * 8;
        float4 u0 = *(const float4*)p, u1 = *(const float4*)(p + 4);
        float uu[8] = {u0.x, u0.y, u0.z, u0.w, u1.x, u1.y, u1.z, u1.w};
        float s = 0.f, s2 = 0.f;
#pragma unroll
        for (int j = 0; j < 8; ++j) { s += uu[j]; s2 += uu[j] * uu[j]; }
#pragma unroll
        for (int off = 16; off > 0; off >>= 1) {
            s  += __shfl_xor_sync(0xffffffffu, s,  off);
            s2 += __shfl_xor_sync(0xffffffffu, s2, off);
        }
        float mu   = s * (1.f / 256.f);
        float var  = s2 * (1.f / 256.f) - mu * mu;
        float rstd = rsqrtf(var + 1e-5f);
        float wv = wts[n * NV + v];
#pragma unroll
        for (int j = 0; j < 8; ++j) {
            int c = lane * 8 + j;
            float y = (uu[j] - mu) * rstd * lng[v * NH + c] + lnb[v * NH + c];
            psum[j] += y * wv;
        }
    }

    *(float4*)(s_part + w * 260 + lane * 8)     = make_float4(psum[0], psum[1], psum[2], psum[3]);
    *(float4*)(s_part + w * 260 + lane * 8 + 4) = make_float4(psum[4], psum[5], psum[6], psum[7]);
    __syncthreads();

    float s = 0.f;
#pragma unroll
    for (int w8 = 0; w8 < 8; ++w8) s += s_part[w8 * 260 + tid];
    out_sel[(size_t)n * NH + tid] = s;
}

// ---------------------------------------------------------------------------
extern "C" void kernel_launch(void* const* d_in, const int* in_sizes, int n_in,
                              void* d_out, int out_size)
{
    const float* x        = (const float*)d_in[0];
    const float* context  = (const float*)d_in[1];
    const float* vg_fc1_w = (const float*)d_in[2];
    const float* vg_fc1_b = (const float*)d_in[3];
    const float* vg_fc2_w = (const float*)d_in[4];
    const float* vg_fc2_b = (const float*)d_in[5];
    const float* vg_glu_w = (const float*)d_in[6];
    const float* vg_glu_b = (const float*)d_in[7];
    const float* vg_skip_w= (const float*)d_in[8];
    const float* vg_skip_b= (const float*)d_in[9];
    const float* vg_ln_g  = (const float*)d_in[10];
    const float* vg_ln_b  = (const float*)d_in[11];
    const float* wg_fc1_w = (const float*)d_in[12];
    const float* wg_fc1_b = (const float*)d_in[13];
    const float* wg_ctx_w = (const float*)d_in[14];
    const float* wg_fc2_w = (const float*)d_in[15];
    const float* wg_fc2_b = (const float*)d_in[16];
    const float* wg_glu_w = (const float*)d_in[17];
    const float* wg_glu_b = (const float*)d_in[18];
    const float* wg_skip_w= (const float*)d_in[19];
    const float* wg_skip_b= (const float*)d_in[20];
    const float* wg_ln_g  = (const float*)d_in[21];
    const float* wg_ln_b  = (const float*)d_in[22];

    float* out      = (float*)d_out;
    float* out_sel  = out;
    float* out_wts  = out + (size_t)NTOK * NH;

    const int WG_SMEM = (128 * PAD + 2 * 256 * PAD + 64 * 16 + 64 * 32) * 4;
    const int G_SMEM  = NS * BK * (GTOK + NH) * 4;   // 80KB/block
    cudaFuncSetAttribute(wg_kernel,      cudaFuncAttributeMaxDynamicSharedMemorySize, WG_SMEM);
    cudaFuncSetAttribute(wgfc1_kernel,   cudaFuncAttributeMaxDynamicSharedMemorySize, G_SMEM);
    cudaFuncSetAttribute(fc1skip_kernel, cudaFuncAttributeMaxDynamicSharedMemorySize, G_SMEM);
    cudaFuncSetAttribute(fc2_kernel,     cudaFuncAttributeMaxDynamicSharedMemorySize, G_SMEM);
    cudaFuncSetAttribute(glu_a_kernel,   cudaFuncAttributeMaxDynamicSharedMemorySize, G_SMEM);
    cudaFuncSetAttribute(glu_b_kernel,   cudaFuncAttributeMaxDynamicSharedMemorySize, G_SMEM);

    const dim3 xgrid(NTOK / GT, NV);
    const dim3 ggrid(NTOK / GTOK, NV);

    ctx_kernel<<<32, NH>>>(context, wg_ctx_w);
    xt_kernel<<<xgrid, 256>>>(x);

    wgfc1_kernel<<<dim3(NTOK / GTOK, 1), 256, G_SMEM>>>(wg_fc1_w, wg_fc1_b);
    wg_kernel<<<NTOK / TT, NTH, WG_SMEM>>>(
        x, wg_fc2_w, wg_fc2_b, wg_glu_w, wg_glu_b,
        wg_skip_w, wg_skip_b, wg_ln_g, wg_ln_b, out_wts);

    fc1skip_kernel<<<ggrid, 256, G_SMEM>>>(vg_fc1_w, vg_fc1_b, vg_skip_w, vg_skip_b);
    fc2_kernel<<<ggrid, 256, G_SMEM>>>(vg_fc2_w, vg_fc2_b);
    glu_a_kernel<<<ggrid, 256, G_SMEM>>>(vg_glu_w, vg_glu_b);
    glu_b_kernel<<<ggrid, 256, G_SMEM>>>(vg_glu_w, vg_glu_b);

    combine_kernel<<<NTOK, 256>>>(vg_ln_g, vg_ln_b, out_wts, out_sel);
}